// round 11
// baseline (speedup 1.0000x reference)
#include <cuda_runtime.h>

// CorrelationMSELoss — B=8192 rows, L=1024 labels, single fused kernel.
// out = mean((pred-label)^2) + sum_rows(row_loss)
// Memory-roofline main loop (proven 12.8us); epilogue uses fire-and-forget
// red.global.add.f64 (REDG) + counter, minimizing the serialized tail.

static constexpr int B_ROWS = 8192;
static constexpr int L_COLS = 1024;
static constexpr int WARPS_PER_BLOCK = 8;
static constexpr int THREADS = WARPS_PER_BLOCK * 32;   // 256
static constexpr int GRID = B_ROWS / WARPS_PER_BLOCK;  // 1024 blocks, one wave

__device__ double g_sum_mse = 0.0;
__device__ double g_sum_loss = 0.0;
__device__ unsigned int g_count = 0;  // reset by last block each launch

__device__ __forceinline__ float ex2_approx(float x) {
    float r;
    asm("ex2.approx.ftz.f32 %0, %1;" : "=f"(r) : "f"(x));
    return r;
}

// fire-and-forget f64 reduction (REDG: no return trip on the critical path)
__device__ __forceinline__ void red_add_f64(double* addr, double v) {
    asm volatile("red.global.add.f64 [%0], %1;" :: "l"(addr), "d"(v) : "memory");
}

__device__ __forceinline__ void accum_chunk(float4 p, float4 l, float& mse,
                                            float& spos, float& stot, float& none) {
    constexpr float L2E = 1.4426950408889634f;  // log2(e)
    float pe[4] = {p.x, p.y, p.z, p.w};
    float le[4] = {l.x, l.y, l.z, l.w};
#pragma unroll
    for (int j = 0; j < 4; ++j) {
        float pv = pe[j], lv = le[j];
        float d = pv - lv;
        mse = fmaf(d, d, mse);
        float t = pv * L2E;
        float arg = fmaf(lv, -2.f * t, t);  // +t for lv=0, -t for lv=1
        float e = ex2_approx(arg);
        stot += e;
        spos = fmaf(lv, e, spos);
        none += lv;  // exact integer count
    }
}

__global__ __launch_bounds__(THREADS) void k_fused(const float* __restrict__ pred,
                                                   const float* __restrict__ label,
                                                   float* __restrict__ out) {
    const int lane = threadIdx.x & 31;
    const int warp = threadIdx.x >> 5;
    const int row = blockIdx.x * WARPS_PER_BLOCK + warp;

    const float4* p4 = reinterpret_cast<const float4*>(pred) + (long)row * (L_COLS / 4) + lane;
    const float4* l4 = reinterpret_cast<const float4*>(label) + (long)row * (L_COLS / 4) + lane;

    float mse = 0.f, spos = 0.f, stot = 0.f, none = 0.f;

#pragma unroll
    for (int i = 0; i < L_COLS / 4 / 32; ++i) {  // 8 iterations
        float4 p = __ldg(p4 + i * 32);
        float4 l = __ldg(l4 + i * 32);
        accum_chunk(p, l, mse, spos, stot, none);
    }

    // warp reduction (warp owns one row)
#pragma unroll
    for (int off = 16; off; off >>= 1) {
        mse  += __shfl_xor_sync(0xffffffffu, mse, off);
        spos += __shfl_xor_sync(0xffffffffu, spos, off);
        stot += __shfl_xor_sync(0xffffffffu, stot, off);
        none += __shfl_xor_sync(0xffffffffu, none, off);
    }

    __shared__ float s_mse[WARPS_PER_BLOCK];
    __shared__ float s_loss[WARPS_PER_BLOCK];

    if (lane == 0) {
        float n1 = none;
        float n0 = (float)L_COLS - none;
        float sneg = stot - spos;
        float loss;
        if (n1 == 0.f) {
            loss = sneg * 0.36787944117144233f / fmaxf(n0, 1.f);  // e^{-1}*s_neg/n0
        } else if (n0 == 0.f) {
            loss = spos / n1;
        } else {
            loss = (spos * sneg) / (n1 * n0);
        }
        s_mse[warp] = mse;
        s_loss[warp] = loss;
    }
    __syncthreads();

    // warp 0 folds the 8 per-warp results; lane 0 accumulates globally
    if (warp == 0) {
        float bm = (lane < WARPS_PER_BLOCK) ? s_mse[lane] : 0.f;
        float bl = (lane < WARPS_PER_BLOCK) ? s_loss[lane] : 0.f;
#pragma unroll
        for (int off = 4; off; off >>= 1) {
            bm += __shfl_xor_sync(0xffffffffu, bm, off);
            bl += __shfl_xor_sync(0xffffffffu, bl, off);
        }
        if (lane == 0) {
            // fire-and-forget sums; membar orders them before the counter bump
            red_add_f64(&g_sum_mse, (double)bm);
            red_add_f64(&g_sum_loss, (double)bl);
            __threadfence();
            unsigned int prev = atomicAdd(&g_count, 1u);
            if (prev == (unsigned)GRID - 1u) {
                // all other blocks' REDGs are globally visible (their fence
                // preceded their counter increment, which we observed)
                __threadfence();
                double tm = g_sum_mse;
                double tl = g_sum_loss;
                out[0] = (float)(tm * (1.0 / ((double)B_ROWS * (double)L_COLS)) + tl);
                // reset for next graph replay (next launch is stream-ordered
                // behind full retirement of this one)
                g_sum_mse = 0.0;
                g_sum_loss = 0.0;
                g_count = 0;
            }
        }
    }
}

extern "C" void kernel_launch(void* const* d_in, const int* in_sizes, int n_in,
                              void* d_out, int out_size) {
    const float* pred  = (const float*)d_in[0];
    const float* label = (const float*)d_in[1];
    float* out = (float*)d_out;
    k_fused<<<GRID, THREADS>>>(pred, label, out);
}

// round 12
// speedup vs baseline: 1.0127x; 1.0127x over previous
#include <cuda_runtime.h>

// CorrelationMSELoss — B=8192 rows, L=1024 labels, single fused kernel.
// out = mean((pred-label)^2) + sum_rows(row_loss)
// Converged memory-roofline main loop; 512-thread blocks halve the number of
// per-CTA epilogues/atomics. Fire-and-forget REDG f64 accumulators + counter.

static constexpr int B_ROWS = 8192;
static constexpr int L_COLS = 1024;
static constexpr int WARPS_PER_BLOCK = 16;
static constexpr int THREADS = WARPS_PER_BLOCK * 32;   // 512
static constexpr int GRID = B_ROWS / WARPS_PER_BLOCK;  // 512 blocks, one wave

__device__ double g_sum_mse = 0.0;
__device__ double g_sum_loss = 0.0;
__device__ unsigned int g_count = 0;  // reset by last block each launch

__device__ __forceinline__ float ex2_approx(float x) {
    float r;
    asm("ex2.approx.ftz.f32 %0, %1;" : "=f"(r) : "f"(x));
    return r;
}

// fire-and-forget f64 reduction (REDG: no return trip on the critical path)
__device__ __forceinline__ void red_add_f64(double* addr, double v) {
    asm volatile("red.global.add.f64 [%0], %1;" :: "l"(addr), "d"(v) : "memory");
}

__device__ __forceinline__ void accum_chunk(float4 p, float4 l, float& mse,
                                            float& spos, float& stot, float& none) {
    constexpr float L2E = 1.4426950408889634f;  // log2(e)
    float pe[4] = {p.x, p.y, p.z, p.w};
    float le[4] = {l.x, l.y, l.z, l.w};
#pragma unroll
    for (int j = 0; j < 4; ++j) {
        float pv = pe[j], lv = le[j];
        float d = pv - lv;
        mse = fmaf(d, d, mse);
        float t = pv * L2E;
        float arg = fmaf(lv, -2.f * t, t);  // +t for lv=0, -t for lv=1
        float e = ex2_approx(arg);
        stot += e;
        spos = fmaf(lv, e, spos);
        none += lv;  // exact integer count
    }
}

__global__ __launch_bounds__(THREADS) void k_fused(const float* __restrict__ pred,
                                                   const float* __restrict__ label,
                                                   float* __restrict__ out) {
    const int lane = threadIdx.x & 31;
    const int warp = threadIdx.x >> 5;
    const int row = blockIdx.x * WARPS_PER_BLOCK + warp;

    const float4* p4 = reinterpret_cast<const float4*>(pred) + (long)row * (L_COLS / 4) + lane;
    const float4* l4 = reinterpret_cast<const float4*>(label) + (long)row * (L_COLS / 4) + lane;

    float mse = 0.f, spos = 0.f, stot = 0.f, none = 0.f;

#pragma unroll
    for (int i = 0; i < L_COLS / 4 / 32; ++i) {  // 8 iterations
        float4 p = __ldg(p4 + i * 32);
        float4 l = __ldg(l4 + i * 32);
        accum_chunk(p, l, mse, spos, stot, none);
    }

    // warp reduction (warp owns one row)
#pragma unroll
    for (int off = 16; off; off >>= 1) {
        mse  += __shfl_xor_sync(0xffffffffu, mse, off);
        spos += __shfl_xor_sync(0xffffffffu, spos, off);
        stot += __shfl_xor_sync(0xffffffffu, stot, off);
        none += __shfl_xor_sync(0xffffffffu, none, off);
    }

    __shared__ float s_mse[WARPS_PER_BLOCK];
    __shared__ float s_loss[WARPS_PER_BLOCK];

    if (lane == 0) {
        float n1 = none;
        float n0 = (float)L_COLS - none;
        float sneg = stot - spos;
        float loss;
        if (n1 == 0.f) {
            loss = sneg * 0.36787944117144233f / fmaxf(n0, 1.f);  // e^{-1}*s_neg/n0
        } else if (n0 == 0.f) {
            loss = spos / n1;
        } else {
            loss = (spos * sneg) / (n1 * n0);
        }
        s_mse[warp] = mse;
        s_loss[warp] = loss;
    }
    __syncthreads();

    // warp 0 folds the 16 per-warp results; lane 0 accumulates globally
    if (warp == 0) {
        float bm = (lane < WARPS_PER_BLOCK) ? s_mse[lane] : 0.f;
        float bl = (lane < WARPS_PER_BLOCK) ? s_loss[lane] : 0.f;
#pragma unroll
        for (int off = 8; off; off >>= 1) {
            bm += __shfl_xor_sync(0xffffffffu, bm, off);
            bl += __shfl_xor_sync(0xffffffffu, bl, off);
        }
        if (lane == 0) {
            // fire-and-forget sums; fence orders them before the counter bump
            red_add_f64(&g_sum_mse, (double)bm);
            red_add_f64(&g_sum_loss, (double)bl);
            __threadfence();
            unsigned int prev = atomicAdd(&g_count, 1u);
            if (prev == (unsigned)GRID - 1u) {
                // all other blocks' REDGs are globally visible (their fence
                // preceded their counter increment, which we observed)
                __threadfence();
                double tm = g_sum_mse;
                double tl = g_sum_loss;
                out[0] = (float)(tm * (1.0 / ((double)B_ROWS * (double)L_COLS)) + tl);
                // reset for next graph replay (next launch is stream-ordered
                // behind full retirement of this one)
                g_sum_mse = 0.0;
                g_sum_loss = 0.0;
                g_count = 0;
            }
        }
    }
}

extern "C" void kernel_launch(void* const* d_in, const int* in_sizes, int n_in,
                              void* d_out, int out_size) {
    const float* pred  = (const float*)d_in[0];
    const float* label = (const float*)d_in[1];
    float* out = (float*)d_out;
    k_fused<<<GRID, THREADS>>>(pred, label, out);
}

// round 13
// speedup vs baseline: 1.1905x; 1.1756x over previous
#include <cuda_runtime.h>

// CorrelationMSELoss — B=8192 rows, L=1024 labels, single fused kernel.
// out = mean((pred-label)^2) + sum_rows(row_loss)
// Converged memory-roofline main loop; 1024-thread blocks (grid 256) minimize
// per-CTA epilogue/atomic/dispatch overhead. REDG f64 accumulators + counter.

static constexpr int B_ROWS = 8192;
static constexpr int L_COLS = 1024;
static constexpr int WARPS_PER_BLOCK = 32;
static constexpr int THREADS = WARPS_PER_BLOCK * 32;   // 1024
static constexpr int GRID = B_ROWS / WARPS_PER_BLOCK;  // 256 blocks, one wave

__device__ double g_sum_mse = 0.0;
__device__ double g_sum_loss = 0.0;
__device__ unsigned int g_count = 0;  // reset by last block each launch

__device__ __forceinline__ float ex2_approx(float x) {
    float r;
    asm("ex2.approx.ftz.f32 %0, %1;" : "=f"(r) : "f"(x));
    return r;
}

// fire-and-forget f64 reduction (REDG: no return trip on the critical path)
__device__ __forceinline__ void red_add_f64(double* addr, double v) {
    asm volatile("red.global.add.f64 [%0], %1;" :: "l"(addr), "d"(v) : "memory");
}

__device__ __forceinline__ void accum_chunk(float4 p, float4 l, float& mse,
                                            float& spos, float& stot, float& none) {
    constexpr float L2E = 1.4426950408889634f;  // log2(e)
    float pe[4] = {p.x, p.y, p.z, p.w};
    float le[4] = {l.x, l.y, l.z, l.w};
#pragma unroll
    for (int j = 0; j < 4; ++j) {
        float pv = pe[j], lv = le[j];
        float d = pv - lv;
        mse = fmaf(d, d, mse);
        float t = pv * L2E;
        float arg = fmaf(lv, -2.f * t, t);  // +t for lv=0, -t for lv=1
        float e = ex2_approx(arg);
        stot += e;
        spos = fmaf(lv, e, spos);
        none += lv;  // exact integer count
    }
}

__global__ __launch_bounds__(THREADS) void k_fused(const float* __restrict__ pred,
                                                   const float* __restrict__ label,
                                                   float* __restrict__ out) {
    const int lane = threadIdx.x & 31;
    const int warp = threadIdx.x >> 5;
    const int row = blockIdx.x * WARPS_PER_BLOCK + warp;

    const float4* p4 = reinterpret_cast<const float4*>(pred) + (long)row * (L_COLS / 4) + lane;
    const float4* l4 = reinterpret_cast<const float4*>(label) + (long)row * (L_COLS / 4) + lane;

    float mse = 0.f, spos = 0.f, stot = 0.f, none = 0.f;

#pragma unroll
    for (int i = 0; i < L_COLS / 4 / 32; ++i) {  // 8 iterations
        float4 p = __ldg(p4 + i * 32);
        float4 l = __ldg(l4 + i * 32);
        accum_chunk(p, l, mse, spos, stot, none);
    }

    // warp reduction (warp owns one row)
#pragma unroll
    for (int off = 16; off; off >>= 1) {
        mse  += __shfl_xor_sync(0xffffffffu, mse, off);
        spos += __shfl_xor_sync(0xffffffffu, spos, off);
        stot += __shfl_xor_sync(0xffffffffu, stot, off);
        none += __shfl_xor_sync(0xffffffffu, none, off);
    }

    __shared__ float s_mse[WARPS_PER_BLOCK];
    __shared__ float s_loss[WARPS_PER_BLOCK];

    if (lane == 0) {
        float n1 = none;
        float n0 = (float)L_COLS - none;
        float sneg = stot - spos;
        float loss;
        if (n1 == 0.f) {
            loss = sneg * 0.36787944117144233f / fmaxf(n0, 1.f);  // e^{-1}*s_neg/n0
        } else if (n0 == 0.f) {
            loss = spos / n1;
        } else {
            loss = (spos * sneg) / (n1 * n0);
        }
        s_mse[warp] = mse;
        s_loss[warp] = loss;
    }
    __syncthreads();

    // warp 0 folds the 32 per-warp results; lane 0 accumulates globally
    if (warp == 0) {
        float bm = s_mse[lane];
        float bl = s_loss[lane];
#pragma unroll
        for (int off = 16; off; off >>= 1) {
            bm += __shfl_xor_sync(0xffffffffu, bm, off);
            bl += __shfl_xor_sync(0xffffffffu, bl, off);
        }
        if (lane == 0) {
            // fire-and-forget sums; fence orders them before the counter bump
            red_add_f64(&g_sum_mse, (double)bm);
            red_add_f64(&g_sum_loss, (double)bl);
            __threadfence();
            unsigned int prev = atomicAdd(&g_count, 1u);
            if (prev == (unsigned)GRID - 1u) {
                // all other blocks' REDGs are globally visible (their fence
                // preceded their counter increment, which we observed)
                __threadfence();
                double tm = g_sum_mse;
                double tl = g_sum_loss;
                out[0] = (float)(tm * (1.0 / ((double)B_ROWS * (double)L_COLS)) + tl);
                // reset for next graph replay (next launch is stream-ordered
                // behind full retirement of this one)
                g_sum_mse = 0.0;
                g_sum_loss = 0.0;
                g_count = 0;
            }
        }
    }
}

extern "C" void kernel_launch(void* const* d_in, const int* in_sizes, int n_in,
                              void* d_out, int out_size) {
    const float* pred  = (const float*)d_in[0];
    const float* label = (const float*)d_in[1];
    float* out = (float*)d_out;
    k_fused<<<GRID, THREADS>>>(pred, label, out);
}